// round 12
// baseline (speedup 1.0000x reference)
#include <cuda_runtime.h>
#include <cstdint>

#define B_ 8
#define N_ 16384
#define M_ 1024
#define C_ 64
#define NS_ 32
#define COUT_ 67
#define R2_ 0.04f

#define FEAT_BLOCKS (B_ * C_)   // 512
#define XYZ_BLOCKS  (B_ * 3)    // 24
#define GD_SMEM ((N_ + M_) * 4) // 69632 bytes

// Scratch: ball-query indices (1 MB).
__device__ int g_idx[(size_t)B_ * M_ * NS_];

// ---------------------------------------------------------------------------
// Ball query helpers: 256-pt chunk = 768 float4; lane owns float4s
// [lane*6, lane*6+6) = points [chunk+8*lane, chunk+8*lane+8).
// ---------------------------------------------------------------------------
struct BqBuf { float4 f[6]; };

__device__ __forceinline__ void bq_load(const float4* __restrict__ base4,
                                        int tfo, BqBuf& b) {
#pragma unroll
    for (int k = 0; k < 6; k++) b.f[k] = base4[tfo + k];
}

__device__ __forceinline__ unsigned bq_mask(const BqBuf& b, float qx, float qy,
                                            float qz) {
    const float* s = (const float*)b.f;
    unsigned m = 0u;
#pragma unroll
    for (int j = 0; j < 8; j++) {
        const float dx = s[3 * j + 0] - qx;
        const float dy = s[3 * j + 1] - qy;
        const float dz = s[3 * j + 2] - qz;
        if (dx * dx + dy * dy + dz * dz < R2_) m |= 1u << j;
    }
    return m;
}

// Hit-chunk path: ordered placement AND count (lane-31 inclusive prefix).
__device__ __forceinline__ int bq_place(unsigned mask, int chunk, int lane,
                                        int total, int* __restrict__ sidxw) {
    const int c = __popc(mask);
    int incl = c;
#pragma unroll
    for (int d = 1; d < 32; d <<= 1) {
        const int v = __shfl_up_sync(0xffffffffu, incl, d);
        if (lane >= d) incl += v;
    }
    int pos = total + (incl - c);
#pragma unroll
    for (int j = 0; j < 8; j++) {
        if ((mask >> j) & 1u) {
            if (pos < NS_) sidxw[pos] = chunk + lane * 8 + j;
            pos++;
        }
    }
    return __shfl_sync(0xffffffffu, incl, 31);
}

// ---------------------------------------------------------------------------
// Kernel 1: ball query. One warp per query. Prefetch distance = 2 chunks:
// loads for n0+512 / n0+768 issue BEFORE the masks of n0 / n0+256 are
// computed, so L2 latency is hidden behind two full chunk periods.
// ---------------------------------------------------------------------------
__global__ void __launch_bounds__(128) ballquery_kernel(
    const float* __restrict__ xyz, const float* __restrict__ new_xyz) {
    __shared__ int sidx[4][NS_];

    const int tid  = threadIdx.x;
    const int w    = tid >> 5;
    const int lane = tid & 31;
    const int q    = blockIdx.x * 4 + w;
    const int b    = q >> 10;

    const float4* base4 = (const float4*)(xyz + (size_t)b * N_ * 3);
    const float*  qp    = new_xyz + (size_t)q * 3;
    const float qx = qp[0], qy = qp[1], qz = qp[2];
    const int tfo = lane * 6;

    int total = 0;
    BqBuf A, B, Cb, D;
    bq_load(base4, 0 * 192 + tfo, A);     // chunk 0
    bq_load(base4, 1 * 192 + tfo, B);     // chunk 256

    for (int n0 = 0; n0 < N_; n0 += 512) {
        // Prefetch chunks n0+512, n0+768 FIRST (consumed 2 periods later).
        const bool more = (n0 + 512) < N_;
        if (more) {
            bq_load(base4, ((n0 + 512) >> 2) * 3 + tfo, Cb);
            bq_load(base4, ((n0 + 768) >> 2) * 3 + tfo, D);
        }
        {
            const unsigned m = bq_mask(A, qx, qy, qz);
            if (__ballot_sync(0xffffffffu, m != 0u)) {
                total += bq_place(m, n0, lane, total, sidx[w]);
                if (total >= NS_) break;
            }
        }
        {
            const unsigned m = bq_mask(B, qx, qy, qz);
            if (__ballot_sync(0xffffffffu, m != 0u)) {
                total += bq_place(m, n0 + 256, lane, total, sidx[w]);
                if (total >= NS_) break;
            }
        }
        if (more) { A = Cb; B = D; }
    }

    __syncwarp();
    int v;
    if (total == 0) {
        v = N_ - 1;  // reference: all-invalid -> clamped gather
    } else {
        const int first = sidx[w][0];
        v = (lane < min(total, NS_)) ? sidx[w][lane] : first;
    }
    g_idx[(size_t)q * NS_ + lane] = v;
}

// ---------------------------------------------------------------------------
// Kernel 2: direct grouping. One 512-thread block per (b, channel).
// idx loads never touch smem, so batch 0 (8-deep) is issued BEFORE
// __syncthreads — its L2 latency hides behind staging + barrier. Gathers for
// batch 0 run while batch 1's idx loads are in flight.
// ---------------------------------------------------------------------------
struct IdxBatch { int4 id[8]; };

__device__ __forceinline__ void load_batch(const int4* __restrict__ ib4,
                                           int t, int e0, IdxBatch& nb) {
#pragma unroll
    for (int j = 0; j < 8; j++) nb.id[j] = ib4[t + (e0 * 8 + j) * 512];
}

__global__ void __launch_bounds__(512) group_direct_kernel(
    const float* __restrict__ xyz, const float* __restrict__ new_xyz,
    const float* __restrict__ feats, float* __restrict__ out) {
    extern __shared__ float row[];           // [N_] (+ [M_] for xyz path)
    const int blk = blockIdx.x;
    const int t   = threadIdx.x;

    if (blk < FEAT_BLOCKS) {
        const int b = blk >> 6;
        const int c = blk & 63;

        const int4* ib4 = (const int4*)(g_idx + (size_t)b * M_ * NS_);
        IdxBatch cur, nxt;
        load_batch(ib4, t, 0, cur);          // in flight during staging+sync

        const float4* src = (const float4*)(feats + ((size_t)b * C_ + c) * N_);
        float4* row4 = (float4*)row;
#pragma unroll
        for (int i = 0; i < 8; i++)
            row4[t + i * 512] = src[t + i * 512];
        __syncthreads();

        float4* ob4 = (float4*)(out + ((size_t)b * COUT_ + 3 + c) * (M_ * NS_));
        // 8192 int4s / 512 threads = 16 per thread = 2 batches of 8.
        load_batch(ib4, t, 1, nxt);          // batch 1 in flight during batch 0
#pragma unroll
        for (int j = 0; j < 8; j++) {
            float4 v;
            v.x = row[cur.id[j].x]; v.y = row[cur.id[j].y];
            v.z = row[cur.id[j].z]; v.w = row[cur.id[j].w];
            ob4[t + j * 512] = v;
        }
#pragma unroll
        for (int j = 0; j < 8; j++) {
            float4 v;
            v.x = row[nxt.id[j].x]; v.y = row[nxt.id[j].y];
            v.z = row[nxt.id[j].z]; v.w = row[nxt.id[j].w];
            ob4[t + (8 + j) * 512] = v;
        }
    } else {
        const int blk2 = blk - FEAT_BLOCKS;
        const int b = blk2 / 3;
        const int c = blk2 % 3;
        float* nq = row + N_;

        const int4* ib4 = (const int4*)(g_idx + (size_t)b * M_ * NS_);
        IdxBatch cur, nxt;
        load_batch(ib4, t, 0, cur);

        for (int i = t; i < N_; i += 512)
            row[i] = xyz[(size_t)b * N_ * 3 + (size_t)i * 3 + c];
        for (int i = t; i < M_; i += 512)
            nq[i] = new_xyz[(size_t)b * M_ * 3 + (size_t)i * 3 + c];
        __syncthreads();

        float4* ob4 = (float4*)(out + ((size_t)b * COUT_ + c) * (M_ * NS_));
        load_batch(ib4, t, 1, nxt);
#pragma unroll
        for (int j = 0; j < 8; j++) {
            const int i4 = t + j * 512;
            const float qv = nq[i4 >> 3];
            float4 v;
            v.x = row[cur.id[j].x] - qv; v.y = row[cur.id[j].y] - qv;
            v.z = row[cur.id[j].z] - qv; v.w = row[cur.id[j].w] - qv;
            ob4[i4] = v;
        }
#pragma unroll
        for (int j = 0; j < 8; j++) {
            const int i4 = t + (8 + j) * 512;
            const float qv = nq[i4 >> 3];
            float4 v;
            v.x = row[nxt.id[j].x] - qv; v.y = row[nxt.id[j].y] - qv;
            v.z = row[nxt.id[j].z] - qv; v.w = row[nxt.id[j].w] - qv;
            ob4[i4] = v;
        }
    }
}

// ---------------------------------------------------------------------------
extern "C" void kernel_launch(void* const* d_in, const int* in_sizes, int n_in,
                              void* d_out, int out_size) {
    const float* xyz = nullptr;
    const float* new_xyz = nullptr;
    const float* feats = nullptr;
    for (int i = 0; i < n_in; i++) {
        if (in_sizes[i] == B_ * N_ * 3)      xyz     = (const float*)d_in[i];
        else if (in_sizes[i] == B_ * M_ * 3) new_xyz = (const float*)d_in[i];
        else if (in_sizes[i] == B_ * C_ * N_) feats  = (const float*)d_in[i];
    }
    float* out = (float*)d_out;

    cudaFuncSetAttribute(group_direct_kernel,
                         cudaFuncAttributeMaxDynamicSharedMemorySize, GD_SMEM);

    ballquery_kernel<<<(B_ * M_) / 4, 128>>>(xyz, new_xyz);
    group_direct_kernel<<<FEAT_BLOCKS + XYZ_BLOCKS, 512, GD_SMEM>>>(
        xyz, new_xyz, feats, out);
}

// round 13
// speedup vs baseline: 1.1140x; 1.1140x over previous
#include <cuda_runtime.h>
#include <cstdint>

#define B_ 8
#define N_ 16384
#define M_ 1024
#define C_ 64
#define NS_ 32
#define COUT_ 67
#define R2_ 0.04f

#define FEAT_BLOCKS (B_ * C_)   // 512
#define XYZ_BLOCKS  (B_ * 3)    // 24
#define GD_SMEM ((N_ + M_) * 4) // 69632 bytes

// Scratch: ball-query indices (1 MB).
__device__ int g_idx[(size_t)B_ * M_ * NS_];

// ---------------------------------------------------------------------------
// Ball query helpers: 256-pt chunk = 768 float4; lane owns float4s
// [lane*6, lane*6+6) = points [chunk+8*lane, chunk+8*lane+8).
// ---------------------------------------------------------------------------
struct BqBuf { float4 f[6]; };

__device__ __forceinline__ void bq_load(const float4* __restrict__ base4,
                                        int tfo, BqBuf& b) {
#pragma unroll
    for (int k = 0; k < 6; k++) b.f[k] = base4[tfo + k];
}

__device__ __forceinline__ unsigned bq_mask(const BqBuf& b, float qx, float qy,
                                            float qz) {
    const float* s = (const float*)b.f;
    unsigned m = 0u;
#pragma unroll
    for (int j = 0; j < 8; j++) {
        const float dx = s[3 * j + 0] - qx;
        const float dy = s[3 * j + 1] - qy;
        const float dz = s[3 * j + 2] - qz;
        if (dx * dx + dy * dy + dz * dz < R2_) m |= 1u << j;
    }
    return m;
}

// Hit-chunk path: ordered placement AND count (lane-31 inclusive prefix).
__device__ __forceinline__ int bq_place(unsigned mask, int chunk, int lane,
                                        int total, int* __restrict__ sidxw) {
    const int c = __popc(mask);
    int incl = c;
#pragma unroll
    for (int d = 1; d < 32; d <<= 1) {
        const int v = __shfl_up_sync(0xffffffffu, incl, d);
        if (lane >= d) incl += v;
    }
    int pos = total + (incl - c);
#pragma unroll
    for (int j = 0; j < 8; j++) {
        if ((mask >> j) & 1u) {
            if (pos < NS_) sidxw[pos] = chunk + lane * 8 + j;
            pos++;
        }
    }
    return __shfl_sync(0xffffffffu, incl, 31);
}

// ---------------------------------------------------------------------------
// Kernel 1: ball query (exact R11 structure — measured best). One warp per
// query, double-buffered 256-pt chunks, one-ballot fast path.
// ---------------------------------------------------------------------------
__global__ void __launch_bounds__(128) ballquery_kernel(
    const float* __restrict__ xyz, const float* __restrict__ new_xyz) {
    __shared__ int sidx[4][NS_];

    const int tid  = threadIdx.x;
    const int w    = tid >> 5;
    const int lane = tid & 31;
    const int q    = blockIdx.x * 4 + w;
    const int b    = q >> 10;

    const float4* base4 = (const float4*)(xyz + (size_t)b * N_ * 3);
    const float*  qp    = new_xyz + (size_t)q * 3;
    const float qx = qp[0], qy = qp[1], qz = qp[2];
    const int tfo = lane * 6;

    int total = 0;
    BqBuf A, B;
    bq_load(base4, 0 * 192 + tfo, A);     // chunk 0
    bq_load(base4, 1 * 192 + tfo, B);     // chunk 256

    for (int n0 = 0; n0 < N_; n0 += 512) {
        {
            const unsigned m = bq_mask(A, qx, qy, qz);
            if (n0 + 512 < N_) bq_load(base4, ((n0 + 512) >> 2) * 3 + tfo, A);
            if (__ballot_sync(0xffffffffu, m != 0u)) {
                total += bq_place(m, n0, lane, total, sidx[w]);
                if (total >= NS_) break;
            }
        }
        {
            const unsigned m = bq_mask(B, qx, qy, qz);
            if (n0 + 768 < N_) bq_load(base4, ((n0 + 768) >> 2) * 3 + tfo, B);
            if (__ballot_sync(0xffffffffu, m != 0u)) {
                total += bq_place(m, n0 + 256, lane, total, sidx[w]);
                if (total >= NS_) break;
            }
        }
    }

    __syncwarp();
    int v;
    if (total == 0) {
        v = N_ - 1;  // reference: all-invalid -> clamped gather
    } else {
        const int first = sidx[w][0];
        v = (lane < min(total, NS_)) ? sidx[w][lane] : first;
    }
    g_idx[(size_t)q * NS_ + lane] = v;
}

// ---------------------------------------------------------------------------
// Kernel 2: direct grouping. One 512-thread block per (b, channel).
// Idx batches of 4 (regs capped at 64 by launch_bounds -> 2 blocks/SM) with
// next-batch loads issued before current-batch gathers. Batch 0 issues
// before __syncthreads, hiding behind row staging + barrier.
// ---------------------------------------------------------------------------
struct IdxBatch4 { int4 id[4]; };

__device__ __forceinline__ void load_batch4(const int4* __restrict__ ib4,
                                            int t, int e0, IdxBatch4& nb) {
#pragma unroll
    for (int j = 0; j < 4; j++) nb.id[j] = ib4[t + (e0 * 4 + j) * 512];
}

__global__ void __launch_bounds__(512, 2) group_direct_kernel(
    const float* __restrict__ xyz, const float* __restrict__ new_xyz,
    const float* __restrict__ feats, float* __restrict__ out) {
    extern __shared__ float row[];           // [N_] (+ [M_] for xyz path)
    const int blk = blockIdx.x;
    const int t   = threadIdx.x;

    if (blk < FEAT_BLOCKS) {
        const int b = blk >> 6;
        const int c = blk & 63;

        const int4* ib4 = (const int4*)(g_idx + (size_t)b * M_ * NS_);
        IdxBatch4 cur, nxt;
        load_batch4(ib4, t, 0, cur);         // in flight during staging+sync

        const float4* src = (const float4*)(feats + ((size_t)b * C_ + c) * N_);
        float4* row4 = (float4*)row;
#pragma unroll
        for (int i = 0; i < 8; i++)
            row4[t + i * 512] = src[t + i * 512];
        __syncthreads();

        float4* ob4 = (float4*)(out + ((size_t)b * COUT_ + 3 + c) * (M_ * NS_));
        // 8192 int4s / 512 threads = 16 per thread = 4 batches of 4.
#pragma unroll
        for (int e0 = 0; e0 < 4; e0++) {
            if (e0 < 3) load_batch4(ib4, t, e0 + 1, nxt);
#pragma unroll
            for (int j = 0; j < 4; j++) {
                float4 v;
                v.x = row[cur.id[j].x]; v.y = row[cur.id[j].y];
                v.z = row[cur.id[j].z]; v.w = row[cur.id[j].w];
                ob4[t + (e0 * 4 + j) * 512] = v;
            }
            cur = nxt;
        }
    } else {
        const int blk2 = blk - FEAT_BLOCKS;
        const int b = blk2 / 3;
        const int c = blk2 % 3;
        float* nq = row + N_;

        const int4* ib4 = (const int4*)(g_idx + (size_t)b * M_ * NS_);
        IdxBatch4 cur, nxt;
        load_batch4(ib4, t, 0, cur);

        for (int i = t; i < N_; i += 512)
            row[i] = xyz[(size_t)b * N_ * 3 + (size_t)i * 3 + c];
        for (int i = t; i < M_; i += 512)
            nq[i] = new_xyz[(size_t)b * M_ * 3 + (size_t)i * 3 + c];
        __syncthreads();

        float4* ob4 = (float4*)(out + ((size_t)b * COUT_ + c) * (M_ * NS_));
#pragma unroll
        for (int e0 = 0; e0 < 4; e0++) {
            if (e0 < 3) load_batch4(ib4, t, e0 + 1, nxt);
#pragma unroll
            for (int j = 0; j < 4; j++) {
                const int i4 = t + (e0 * 4 + j) * 512;
                const float qv = nq[i4 >> 3];
                float4 v;
                v.x = row[cur.id[j].x] - qv; v.y = row[cur.id[j].y] - qv;
                v.z = row[cur.id[j].z] - qv; v.w = row[cur.id[j].w] - qv;
                ob4[i4] = v;
            }
            cur = nxt;
        }
    }
}

// ---------------------------------------------------------------------------
extern "C" void kernel_launch(void* const* d_in, const int* in_sizes, int n_in,
                              void* d_out, int out_size) {
    const float* xyz = nullptr;
    const float* new_xyz = nullptr;
    const float* feats = nullptr;
    for (int i = 0; i < n_in; i++) {
        if (in_sizes[i] == B_ * N_ * 3)      xyz     = (const float*)d_in[i];
        else if (in_sizes[i] == B_ * M_ * 3) new_xyz = (const float*)d_in[i];
        else if (in_sizes[i] == B_ * C_ * N_) feats  = (const float*)d_in[i];
    }
    float* out = (float*)d_out;

    cudaFuncSetAttribute(group_direct_kernel,
                         cudaFuncAttributeMaxDynamicSharedMemorySize, GD_SMEM);

    ballquery_kernel<<<(B_ * M_) / 4, 128>>>(xyz, new_xyz);
    group_direct_kernel<<<FEAT_BLOCKS + XYZ_BLOCKS, 512, GD_SMEM>>>(
        xyz, new_xyz, feats, out);
}

// round 14
// speedup vs baseline: 1.1490x; 1.0314x over previous
#include <cuda_runtime.h>
#include <cstdint>

#define B_ 8
#define N_ 16384
#define M_ 1024
#define C_ 64
#define NS_ 32
#define COUT_ 67
#define R2_ 0.04f

#define FEAT_BLOCKS (B_ * C_)   // 512
#define XYZ_BLOCKS  (B_ * 3)    // 24
#define GD_SMEM ((N_ + M_) * 4) // 69632 bytes
#define BQT 512                 // ball-query tile points
#define NTILE (N_ / BQT)        // 32

// Scratch: ball-query indices (1 MB).
__device__ int g_idx[(size_t)B_ * M_ * NS_];

// ---------------------------------------------------------------------------
// Kernel 1: ball query — block-shared smem tiles, warp<->query 1:1.
// 128-thr block = 4 warps = 4 queries (same batch). Double-buffered 512-pt
// tiles: prefetch tile t+1 into regs, scan tile t from smem (float4-padded,
// LDS.128 conflict-free), STS, sync. Fast path per 256-pt chunk: 24 FMA +
// ONE ballot; 8-ballot ordered placement only on hit-chunks. Early exit when
// all 4 queries done. L2 read traffic ~4x lower than per-warp streaming.
// ---------------------------------------------------------------------------
__global__ void __launch_bounds__(128) ballquery_kernel(
    const float* __restrict__ xyz, const float* __restrict__ new_xyz) {
    __shared__ float4 sp[2][BQT];        // 16 KB
    __shared__ int    sidx[4][NS_];
    __shared__ int    s_done;

    const int tid  = threadIdx.x;
    const int w    = tid >> 5;
    const int lane = tid & 31;
    const int q    = blockIdx.x * 4 + w;
    const int b    = q >> 10;

    const float4* src4 = (const float4*)(xyz + (size_t)b * N_ * 3);
    const float*  qp   = new_xyz + (size_t)q * 3;
    const float qx = qp[0], qy = qp[1], qz = qp[2];
    const unsigned ltm = (1u << lane) - 1u;

    if (tid == 0) s_done = 0;

    // Tile t = float4s [384t, 384(t+1)); thread owns 3 float4 = 4 points.
    float4 ra, rb, rc;
    {
        const int fb = 3 * tid;
        ra = src4[fb]; rb = src4[fb + 1]; rc = src4[fb + 2];
        sp[0][4 * tid + 0] = make_float4(ra.x, ra.y, ra.z, 0.f);
        sp[0][4 * tid + 1] = make_float4(ra.w, rb.x, rb.y, 0.f);
        sp[0][4 * tid + 2] = make_float4(rb.z, rb.w, rc.x, 0.f);
        sp[0][4 * tid + 3] = make_float4(rc.y, rc.z, rc.w, 0.f);
    }
    __syncthreads();

    int  total   = 0;
    bool done    = false;
    bool counted = false;

    for (int t = 0; t < NTILE; t++) {
        const bool more = (t + 1) < NTILE;
        if (more) {                       // prefetch tile t+1 into registers
            const int fb = 384 * (t + 1) + 3 * tid;
            ra = src4[fb]; rb = src4[fb + 1]; rc = src4[fb + 2];
        }

        if (!done) {
            const float4* tp = sp[t & 1];
#pragma unroll
            for (int ch = 0; ch < 2; ch++) {
                unsigned m = 0u;
#pragma unroll
                for (int j = 0; j < 8; j++) {
                    const float4 p = tp[ch * 256 + j * 32 + lane];
                    const float dx = p.x - qx, dy = p.y - qy, dz = p.z - qz;
                    if (dx * dx + dy * dy + dz * dz < R2_) m |= 1u << j;
                }
                if (__ballot_sync(0xffffffffu, m != 0u)) {
                    // placement: order = 512t + 256ch + 32j + lane
                    int run = total;
#pragma unroll
                    for (int j = 0; j < 8; j++) {
                        const unsigned bm =
                            __ballot_sync(0xffffffffu, (m >> j) & 1u);
                        if (bm) {
                            const int pos = run + __popc(bm & ltm);
                            if (((m >> j) & 1u) && pos < NS_)
                                sidx[w][pos] =
                                    BQT * t + 256 * ch + 32 * j + lane;
                            run += __popc(bm);
                        }
                    }
                    total = run;
                    if (total >= NS_) { done = true; break; }
                }
            }
            if (done && !counted) {
                counted = true;
                if (lane == 0) atomicAdd(&s_done, 1);
            }
        }

        if (more) {                       // stage tile t+1
            sp[(t + 1) & 1][4 * tid + 0] = make_float4(ra.x, ra.y, ra.z, 0.f);
            sp[(t + 1) & 1][4 * tid + 1] = make_float4(ra.w, rb.x, rb.y, 0.f);
            sp[(t + 1) & 1][4 * tid + 2] = make_float4(rb.z, rb.w, rc.x, 0.f);
            sp[(t + 1) & 1][4 * tid + 3] = make_float4(rc.y, rc.z, rc.w, 0.f);
        }
        __syncthreads();
        if (s_done == 4) break;
    }

    __syncwarp();
    int v;
    if (total == 0) {
        v = N_ - 1;  // reference: all-invalid -> clamped gather
    } else {
        const int first = sidx[w][0];
        v = (lane < min(total, NS_)) ? sidx[w][lane] : first;
    }
    g_idx[(size_t)q * NS_ + lane] = v;
}

// ---------------------------------------------------------------------------
// Kernel 2: direct grouping (exact R11 form — measured best, 28.1us).
// One 512-thread block per (b, channel): stage the channel row in smem
// (coalesced float4), gather with 4-deep batched int4 idx loads + STG.128.
// ---------------------------------------------------------------------------
__global__ void __launch_bounds__(512) group_direct_kernel(
    const float* __restrict__ xyz, const float* __restrict__ new_xyz,
    const float* __restrict__ feats, float* __restrict__ out) {
    extern __shared__ float row[];           // [N_] (+ [M_] for xyz path)
    const int blk = blockIdx.x;
    const int t   = threadIdx.x;

    if (blk < FEAT_BLOCKS) {
        const int b = blk >> 6;
        const int c = blk & 63;

        const float4* src = (const float4*)(feats + ((size_t)b * C_ + c) * N_);
        float4* row4 = (float4*)row;
#pragma unroll
        for (int i = 0; i < 8; i++)
            row4[t + i * 512] = src[t + i * 512];
        __syncthreads();

        const int4* ib4 = (const int4*)(g_idx + (size_t)b * M_ * NS_);
        float4* ob4 = (float4*)(out + ((size_t)b * COUT_ + 3 + c) * (M_ * NS_));
#pragma unroll
        for (int e0 = 0; e0 < 4; e0++) {
            int4 id[4];
#pragma unroll
            for (int j = 0; j < 4; j++)
                id[j] = ib4[t + (e0 * 4 + j) * 512];
#pragma unroll
            for (int j = 0; j < 4; j++) {
                float4 v;
                v.x = row[id[j].x]; v.y = row[id[j].y];
                v.z = row[id[j].z]; v.w = row[id[j].w];
                ob4[t + (e0 * 4 + j) * 512] = v;
            }
        }
    } else {
        const int blk2 = blk - FEAT_BLOCKS;
        const int b = blk2 / 3;
        const int c = blk2 % 3;
        float* nq = row + N_;

        for (int i = t; i < N_; i += 512)
            row[i] = xyz[(size_t)b * N_ * 3 + (size_t)i * 3 + c];
        for (int i = t; i < M_; i += 512)
            nq[i] = new_xyz[(size_t)b * M_ * 3 + (size_t)i * 3 + c];
        __syncthreads();

        const int4* ib4 = (const int4*)(g_idx + (size_t)b * M_ * NS_);
        float4* ob4 = (float4*)(out + ((size_t)b * COUT_ + c) * (M_ * NS_));
#pragma unroll
        for (int e0 = 0; e0 < 4; e0++) {
            int4 id[4];
#pragma unroll
            for (int j = 0; j < 4; j++)
                id[j] = ib4[t + (e0 * 4 + j) * 512];
#pragma unroll
            for (int j = 0; j < 4; j++) {
                const int i4 = t + (e0 * 4 + j) * 512;
                const float qv = nq[i4 >> 3];
                float4 v;
                v.x = row[id[j].x] - qv; v.y = row[id[j].y] - qv;
                v.z = row[id[j].z] - qv; v.w = row[id[j].w] - qv;
                ob4[i4] = v;
            }
        }
    }
}

// ---------------------------------------------------------------------------
extern "C" void kernel_launch(void* const* d_in, const int* in_sizes, int n_in,
                              void* d_out, int out_size) {
    const float* xyz = nullptr;
    const float* new_xyz = nullptr;
    const float* feats = nullptr;
    for (int i = 0; i < n_in; i++) {
        if (in_sizes[i] == B_ * N_ * 3)      xyz     = (const float*)d_in[i];
        else if (in_sizes[i] == B_ * M_ * 3) new_xyz = (const float*)d_in[i];
        else if (in_sizes[i] == B_ * C_ * N_) feats  = (const float*)d_in[i];
    }
    float* out = (float*)d_out;

    cudaFuncSetAttribute(group_direct_kernel,
                         cudaFuncAttributeMaxDynamicSharedMemorySize, GD_SMEM);

    ballquery_kernel<<<(B_ * M_) / 4, 128>>>(xyz, new_xyz);
    group_direct_kernel<<<FEAT_BLOCKS + XYZ_BLOCKS, 512, GD_SMEM>>>(
        xyz, new_xyz, feats, out);
}